// round 3
// baseline (speedup 1.0000x reference)
#include <cuda_runtime.h>

// out[b, d] = initial[b, d] * (sum_k X[b,k]*alphas[k]) + X[b,d] + bias[d]
// B = 16384 rows, D = 2048 cols, fp32.
//
// Persistent-CTA version: grid = 148 SMs * 8 CTAs = 1184 blocks of 256
// threads; each CTA loops over rows with stride gridDim.x. alphas and bias
// (shared by every row) are loaded into registers ONCE, eliminating ~256 MB
// of per-row L2->L1 traffic. CTAs drift out of phase across iterations,
// smoothing the HBM read/write mix.

#define THREADS 256
#define D_DIM 2048
#define GRID_CTAS (148 * 8)

__global__ __launch_bounds__(THREADS, 8)
void crossnet_kernel(const float* __restrict__ initial,
                     const float* __restrict__ X,
                     const float* __restrict__ alphas,
                     const float* __restrict__ bias,
                     float* __restrict__ out,
                     int B)
{
    const int t = threadIdx.x;
    const int lane = t & 31;
    const int wid = t >> 5;

    // Row-invariant operands: load once, keep in registers.
    const float4* __restrict__ A4 = reinterpret_cast<const float4*>(alphas);
    const float4* __restrict__ B4 = reinterpret_cast<const float4*>(bias);
    const float4 a0 = A4[t];
    const float4 a1 = A4[t + THREADS];
    const float4 b0 = B4[t];
    const float4 b1 = B4[t + THREADS];

    __shared__ float warp_sums[THREADS / 32];
    __shared__ float scale_sh;

    for (int row = blockIdx.x; row < B; row += GRID_CTAS) {
        const float4* __restrict__ X4 =
            reinterpret_cast<const float4*>(X) + (size_t)row * (D_DIM / 4);
        const float4* __restrict__ I4 =
            reinterpret_cast<const float4*>(initial) + (size_t)row * (D_DIM / 4);
        float4* __restrict__ O4 =
            reinterpret_cast<float4*>(out) + (size_t)row * (D_DIM / 4);

        // Front-batched streaming loads (single-use rows -> evict-first).
        float4 x0 = __ldcs(&X4[t]);
        float4 x1 = __ldcs(&X4[t + THREADS]);
        float4 i0 = __ldcs(&I4[t]);
        float4 i1 = __ldcs(&I4[t + THREADS]);

        // Per-thread partial dot product.
        float dot = x0.x * a0.x + x0.y * a0.y + x0.z * a0.z + x0.w * a0.w
                  + x1.x * a1.x + x1.y * a1.y + x1.z * a1.z + x1.w * a1.w;

        // Warp reduce.
        #pragma unroll
        for (int off = 16; off > 0; off >>= 1)
            dot += __shfl_xor_sync(0xFFFFFFFFu, dot, off);

        // Block reduce across 8 warps.
        if (lane == 0) warp_sums[wid] = dot;
        __syncthreads();
        if (wid == 0) {
            float s = (lane < THREADS / 32) ? warp_sums[lane] : 0.0f;
            #pragma unroll
            for (int off = 4; off > 0; off >>= 1)
                s += __shfl_xor_sync(0xFFFFFFFFu, s, off);
            if (lane == 0) scale_sh = s;
        }
        __syncthreads();
        const float scale = scale_sh;

        float4 o0, o1;
        o0.x = fmaf(i0.x, scale, x0.x + b0.x);
        o0.y = fmaf(i0.y, scale, x0.y + b0.y);
        o0.z = fmaf(i0.z, scale, x0.z + b0.z);
        o0.w = fmaf(i0.w, scale, x0.w + b0.w);
        o1.x = fmaf(i1.x, scale, x1.x + b1.x);
        o1.y = fmaf(i1.y, scale, x1.y + b1.y);
        o1.z = fmaf(i1.z, scale, x1.z + b1.z);
        o1.w = fmaf(i1.w, scale, x1.w + b1.w);

        // Output never re-read -> streaming store.
        __stcs(&O4[t], o0);
        __stcs(&O4[t + THREADS], o1);

        // Barrier before next iteration reuses scale_sh / warp_sums.
        __syncthreads();
    }
}

extern "C" void kernel_launch(void* const* d_in, const int* in_sizes, int n_in,
                              void* d_out, int out_size)
{
    const float* initial = (const float*)d_in[0];
    const float* X       = (const float*)d_in[1];
    const float* alphas  = (const float*)d_in[2];
    const float* bias    = (const float*)d_in[3];
    float* out           = (float*)d_out;

    const int B = in_sizes[0] / D_DIM;   // 16384
    crossnet_kernel<<<GRID_CTAS, THREADS>>>(initial, X, alphas, bias, out, B);
}

// round 4
// speedup vs baseline: 1.1194x; 1.1194x over previous
#include <cuda_runtime.h>

// out[b, d] = initial[b, d] * (sum_k X[b,k]*alphas[k]) + X[b,d] + bias[d]
// B = 16384 rows, D = 2048 cols, fp32.
//
// One CTA per row (fast CTA churn keeps independent loads in flight).
// 256 threads x 2 float4 = 2048 elements. Single-barrier block reduction:
// each warp writes its partial, one __syncthreads, then every warp
// redundantly reduces the 8 partials via shuffle -- no second barrier.

#define THREADS 256
#define D_DIM 2048
#define NWARPS (THREADS / 32)

__global__ __launch_bounds__(THREADS, 8)
void crossnet_kernel(const float* __restrict__ initial,
                     const float* __restrict__ X,
                     const float* __restrict__ alphas,
                     const float* __restrict__ bias,
                     float* __restrict__ out)
{
    const int row = blockIdx.x;
    const int t = threadIdx.x;
    const int lane = t & 31;
    const int wid = t >> 5;

    const float4* __restrict__ X4 = reinterpret_cast<const float4*>(X) + (size_t)row * (D_DIM / 4);
    const float4* __restrict__ I4 = reinterpret_cast<const float4*>(initial) + (size_t)row * (D_DIM / 4);
    const float4* __restrict__ A4 = reinterpret_cast<const float4*>(alphas);
    const float4* __restrict__ B4 = reinterpret_cast<const float4*>(bias);
    float4* __restrict__ O4 = reinterpret_cast<float4*>(out) + (size_t)row * (D_DIM / 4);

    // Front-batched loads. Single-use rows stream (.cs); alphas/bias stay hot.
    float4 x0 = __ldcs(&X4[t]);
    float4 x1 = __ldcs(&X4[t + THREADS]);
    float4 i0 = __ldcs(&I4[t]);
    float4 i1 = __ldcs(&I4[t + THREADS]);
    float4 a0 = A4[t];
    float4 a1 = A4[t + THREADS];
    float4 b0 = B4[t];
    float4 b1 = B4[t + THREADS];

    // Per-thread partial dot product.
    float dot = x0.x * a0.x + x0.y * a0.y + x0.z * a0.z + x0.w * a0.w
              + x1.x * a1.x + x1.y * a1.y + x1.z * a1.z + x1.w * a1.w;

    // Warp reduce.
    #pragma unroll
    for (int off = 16; off > 0; off >>= 1)
        dot += __shfl_xor_sync(0xFFFFFFFFu, dot, off);

    // Single-barrier block reduce: every warp redundantly folds the 8
    // partials, so no second barrier / smem broadcast is needed.
    __shared__ float warp_sums[NWARPS];
    if (lane == 0) warp_sums[wid] = dot;
    __syncthreads();

    float s = (lane < NWARPS) ? warp_sums[lane] : 0.0f;
    #pragma unroll
    for (int off = NWARPS / 2; off > 0; off >>= 1)
        s += __shfl_xor_sync(0xFFFFFFFFu, s, off);
    const float scale = __shfl_sync(0xFFFFFFFFu, s, 0);

    float4 o0, o1;
    o0.x = fmaf(i0.x, scale, x0.x + b0.x);
    o0.y = fmaf(i0.y, scale, x0.y + b0.y);
    o0.z = fmaf(i0.z, scale, x0.z + b0.z);
    o0.w = fmaf(i0.w, scale, x0.w + b0.w);
    o1.x = fmaf(i1.x, scale, x1.x + b1.x);
    o1.y = fmaf(i1.y, scale, x1.y + b1.y);
    o1.z = fmaf(i1.z, scale, x1.z + b1.z);
    o1.w = fmaf(i1.w, scale, x1.w + b1.w);

    // Output never re-read -> streaming store.
    __stcs(&O4[t], o0);
    __stcs(&O4[t + THREADS], o1);
}

extern "C" void kernel_launch(void* const* d_in, const int* in_sizes, int n_in,
                              void* d_out, int out_size)
{
    const float* initial = (const float*)d_in[0];
    const float* X       = (const float*)d_in[1];
    const float* alphas  = (const float*)d_in[2];
    const float* bias    = (const float*)d_in[3];
    float* out           = (float*)d_out;

    const int B = in_sizes[0] / D_DIM;   // 16384
    crossnet_kernel<<<B, THREADS>>>(initial, X, alphas, bias, out);
}

// round 5
// speedup vs baseline: 1.1200x; 1.0005x over previous
#include <cuda_runtime.h>

// out[b, d] = initial[b, d] * (sum_k X[b,k]*alphas[k]) + X[b,d] + bias[d]
// B = 16384 rows, D = 2048 cols, fp32.
//
// TWO rows per CTA: 256 threads, each thread covers 2 float4 per row per
// array. 8 streaming float4 LDGs front-batched per thread (deeper MLP), one
// barrier + one smem round-trip serves BOTH row reductions. Grid = B/2.

#define THREADS 256
#define D_DIM 2048
#define D4 (D_DIM / 4)          // 512 float4 per row
#define NWARPS (THREADS / 32)   // 8

__global__ __launch_bounds__(THREADS, 4)
void crossnet_kernel(const float* __restrict__ initial,
                     const float* __restrict__ X,
                     const float* __restrict__ alphas,
                     const float* __restrict__ bias,
                     float* __restrict__ out)
{
    const int t = threadIdx.x;
    const int lane = t & 31;
    const int wid = t >> 5;

    const size_t base0 = (size_t)(2 * blockIdx.x) * D4;
    const size_t base1 = base0 + D4;

    const float4* __restrict__ X4 = reinterpret_cast<const float4*>(X);
    const float4* __restrict__ I4 = reinterpret_cast<const float4*>(initial);
    const float4* __restrict__ A4 = reinterpret_cast<const float4*>(alphas);
    const float4* __restrict__ B4 = reinterpret_cast<const float4*>(bias);
    float4* __restrict__ O4 = reinterpret_cast<float4*>(out);

    // Front-batched streaming loads: both rows of X and initial (8 LDG.128),
    // plus cached alphas/bias (4 LDG.128, L1/L2-hot).
    float4 x00 = __ldcs(&X4[base0 + t]);
    float4 x01 = __ldcs(&X4[base0 + t + THREADS]);
    float4 x10 = __ldcs(&X4[base1 + t]);
    float4 x11 = __ldcs(&X4[base1 + t + THREADS]);
    float4 i00 = __ldcs(&I4[base0 + t]);
    float4 i01 = __ldcs(&I4[base0 + t + THREADS]);
    float4 i10 = __ldcs(&I4[base1 + t]);
    float4 i11 = __ldcs(&I4[base1 + t + THREADS]);
    float4 a0 = A4[t];
    float4 a1 = A4[t + THREADS];
    float4 b0 = B4[t];
    float4 b1 = B4[t + THREADS];

    // Per-thread partial dot products for both rows.
    float dot0 = x00.x * a0.x + x00.y * a0.y + x00.z * a0.z + x00.w * a0.w
               + x01.x * a1.x + x01.y * a1.y + x01.z * a1.z + x01.w * a1.w;
    float dot1 = x10.x * a0.x + x10.y * a0.y + x10.z * a0.z + x10.w * a0.w
               + x11.x * a1.x + x11.y * a1.y + x11.z * a1.z + x11.w * a1.w;

    // Warp reduce both rows.
    #pragma unroll
    for (int off = 16; off > 0; off >>= 1) {
        dot0 += __shfl_xor_sync(0xFFFFFFFFu, dot0, off);
        dot1 += __shfl_xor_sync(0xFFFFFFFFu, dot1, off);
    }

    // One barrier serves both rows' block reductions.
    __shared__ float ws0[NWARPS];
    __shared__ float ws1[NWARPS];
    if (lane == 0) { ws0[wid] = dot0; ws1[wid] = dot1; }
    __syncthreads();

    float s0 = (lane < NWARPS) ? ws0[lane] : 0.0f;
    float s1 = (lane < NWARPS) ? ws1[lane] : 0.0f;
    #pragma unroll
    for (int off = NWARPS / 2; off > 0; off >>= 1) {
        s0 += __shfl_xor_sync(0xFFFFFFFFu, s0, off);
        s1 += __shfl_xor_sync(0xFFFFFFFFu, s1, off);
    }
    const float scale0 = __shfl_sync(0xFFFFFFFFu, s0, 0);
    const float scale1 = __shfl_sync(0xFFFFFFFFu, s1, 0);

    float4 o;
    o.x = fmaf(i00.x, scale0, x00.x + b0.x);
    o.y = fmaf(i00.y, scale0, x00.y + b0.y);
    o.z = fmaf(i00.z, scale0, x00.z + b0.z);
    o.w = fmaf(i00.w, scale0, x00.w + b0.w);
    __stcs(&O4[base0 + t], o);

    o.x = fmaf(i01.x, scale0, x01.x + b1.x);
    o.y = fmaf(i01.y, scale0, x01.y + b1.y);
    o.z = fmaf(i01.z, scale0, x01.z + b1.z);
    o.w = fmaf(i01.w, scale0, x01.w + b1.w);
    __stcs(&O4[base0 + t + THREADS], o);

    o.x = fmaf(i10.x, scale1, x10.x + b0.x);
    o.y = fmaf(i10.y, scale1, x10.y + b0.y);
    o.z = fmaf(i10.z, scale1, x10.z + b0.z);
    o.w = fmaf(i10.w, scale1, x10.w + b0.w);
    __stcs(&O4[base1 + t], o);

    o.x = fmaf(i11.x, scale1, x11.x + b1.x);
    o.y = fmaf(i11.y, scale1, x11.y + b1.y);
    o.z = fmaf(i11.z, scale1, x11.z + b1.z);
    o.w = fmaf(i11.w, scale1, x11.w + b1.w);
    __stcs(&O4[base1 + t + THREADS], o);
}

extern "C" void kernel_launch(void* const* d_in, const int* in_sizes, int n_in,
                              void* d_out, int out_size)
{
    const float* initial = (const float*)d_in[0];
    const float* X       = (const float*)d_in[1];
    const float* alphas  = (const float*)d_in[2];
    const float* bias    = (const float*)d_in[3];
    float* out           = (float*)d_out;

    const int B = in_sizes[0] / D_DIM;   // 16384
    crossnet_kernel<<<B / 2, THREADS>>>(initial, X, alphas, bias, out);
}